// round 8
// baseline (speedup 1.0000x reference)
#include <cuda_runtime.h>
#include <cuda_bf16.h>
#include <cstdint>

#define VOCAB   32000
#define EMB_DIM 2048
#define N_COMP  64
#define SEQ_L   128
#define BATCH   4096
#define SPLIT   8

// ---------------------------------------------------------------------------
// Static scratch (no allocation)
// ---------------------------------------------------------------------------
__device__ float         g_part[SPLIT][N_COMP * EMB_DIM];   // pool partials (4 MB)
__device__ __nv_bfloat16 g_BT_hi[EMB_DIM * N_COMP];         // pooled^T hi [n][k]
__device__ __nv_bfloat16 g_BT_lo[EMB_DIM * N_COMP];         // pooled^T lo [n][k]
__device__ __nv_bfloat16 g_A_hi[BATCH * N_COMP];            // ratio hi [b][k]
__device__ __nv_bfloat16 g_A_lo[BATCH * N_COMP];            // ratio lo [b][k]

// ---------------------------------------------------------------------------
// Kernel 1: pooled partial sums (exact R5). grid=(N_COMP,4,SPLIT), block=128.
// ---------------------------------------------------------------------------
__global__ void pool_kernel(const int* __restrict__ ids,
                            const float* __restrict__ emb) {
    __shared__ int s_ids[SEQ_L / SPLIT];
    const int comp = blockIdx.x;
    const int z = blockIdx.z;
    const int t = threadIdx.x;
    const int TOK = SEQ_L / SPLIT;              // 16
    if (t < TOK) s_ids[t] = ids[comp * SEQ_L + z * TOK + t];
    __syncthreads();

    const int col4 = blockIdx.y * 128 + t;      // 0..511
    const float4* __restrict__ emb4 = (const float4*)emb;

    float4 acc = make_float4(0.f, 0.f, 0.f, 0.f);
#pragma unroll
    for (int l = 0; l < TOK; l++) {
        const int row = s_ids[l];
        float4 v = __ldg(&emb4[(size_t)row * (EMB_DIM / 4) + col4]);
        acc.x += v.x; acc.y += v.y; acc.z += v.z; acc.w += v.w;
    }
    ((float4*)g_part[z])[comp * (EMB_DIM / 4) + col4] = acc;
}

// ---------------------------------------------------------------------------
// bf16 split helpers
// ---------------------------------------------------------------------------
__device__ __forceinline__ void split_bf16(float v, __nv_bfloat16& hi, __nv_bfloat16& lo) {
    hi = __float2bfloat16_rn(v);
    lo = __float2bfloat16_rn(v - __bfloat162float(hi));
}
__device__ __forceinline__ uint32_t pack_bf2(__nv_bfloat16 a, __nv_bfloat16 b) {
    __nv_bfloat162 h = __halves2bfloat162(a, b);
    return *reinterpret_cast<uint32_t*>(&h);
}

// ---------------------------------------------------------------------------
// Kernel 2: converts. blocks 0..63: pooled reduce+scale+split+transpose.
//           blocks 64..319: ratio fp32 -> bf16 hi/lo (2 float4 per thread).
// ---------------------------------------------------------------------------
__global__ void cvt_kernel(const float* __restrict__ ratio) {
    const int bx = blockIdx.x;
    if (bx < 64) {
        const int lane = threadIdx.x & 31;
        const int ty = threadIdx.x >> 5;            // 0..3
        const int n = bx * 32 + lane;               // 0..2047
        const int k0 = ty * 16;

        uint32_t h2[8], l2[8];
#pragma unroll
        for (int kp = 0; kp < 8; kp++) {
            __nv_bfloat16 ha, la, hb, lb;
            {
                const int k = k0 + 2 * kp;
                float s = 0.f;
#pragma unroll
                for (int z = 0; z < SPLIT; z++) s += g_part[z][k * EMB_DIM + n];
                split_bf16(s * (1.0f / SEQ_L), ha, la);
            }
            {
                const int k = k0 + 2 * kp + 1;
                float s = 0.f;
#pragma unroll
                for (int z = 0; z < SPLIT; z++) s += g_part[z][k * EMB_DIM + n];
                split_bf16(s * (1.0f / SEQ_L), hb, lb);
            }
            h2[kp] = pack_bf2(ha, hb);
            l2[kp] = pack_bf2(la, lb);
        }
        uint4* dh = (uint4*)g_BT_hi;   // row n = 8 uint4 (64 bf16)
        uint4* dl = (uint4*)g_BT_lo;
#pragma unroll
        for (int c = 0; c < 2; c++) {
            dh[n * 8 + ty * 2 + c] = make_uint4(h2[4*c], h2[4*c+1], h2[4*c+2], h2[4*c+3]);
            dl[n * 8 + ty * 2 + c] = make_uint4(l2[4*c], l2[4*c+1], l2[4*c+2], l2[4*c+3]);
        }
    } else {
        const int base = (bx - 64) * 256 + threadIdx.x * 2;   // float4 index, 2 each
#pragma unroll
        for (int j = 0; j < 2; j++) {
            const int gid = base + j;                          // 0..65535
            float4 v = __ldg(&((const float4*)ratio)[gid]);
            __nv_bfloat16 h0, l0, h1, l1, h2, l2, h3, l3;
            split_bf16(v.x, h0, l0); split_bf16(v.y, h1, l1);
            split_bf16(v.z, h2, l2); split_bf16(v.w, h3, l3);
            ((uint2*)g_A_hi)[gid] = make_uint2(pack_bf2(h0, h1), pack_bf2(h2, h3));
            ((uint2*)g_A_lo)[gid] = make_uint2(pack_bf2(l0, l1), pack_bf2(l2, l3));
        }
    }
}

// ---------------------------------------------------------------------------
// Kernel 3: HMMA mix, high-occupancy version.
// CTA: 128 b-rows x 64 d-cols, 256 threads = 8 warps, warp tile 16m x 64n.
// A fragments: direct LDG.32 from g_A_hi/lo (L1/L2-hot).
// B: smem (18.4 KB) + ldmatrix, 144B-padded rows.
// ---------------------------------------------------------------------------
#define MMA16816(c, a, b0, b1) \
    asm volatile("mma.sync.aligned.m16n8k16.row.col.f32.bf16.bf16.f32 " \
        "{%0,%1,%2,%3}, {%4,%5,%6,%7}, {%8,%9}, {%0,%1,%2,%3};" \
        : "+f"((c)[0]), "+f"((c)[1]), "+f"((c)[2]), "+f"((c)[3]) \
        : "r"((a)[0]), "r"((a)[1]), "r"((a)[2]), "r"((a)[3]), "r"(b0), "r"(b1))

#define LDSM_X4(r0, r1, r2, r3, addr) \
    asm volatile("ldmatrix.sync.aligned.m8n8.x4.shared.b16 {%0,%1,%2,%3}, [%4];" \
        : "=r"(r0), "=r"(r1), "=r"(r2), "=r"(r3) : "r"(addr))

#define ROWB 144            // padded row pitch in bytes (72 bf16)

__device__ __forceinline__ uint32_t smem_u32(const void* p) {
    uint32_t a;
    asm("{ .reg .u64 t; cvta.to.shared.u64 t, %1; cvt.u32.u64 %0, t; }" : "=r"(a) : "l"(p));
    return a;
}

__global__ void __launch_bounds__(256, 4)
mix_kernel(float* __restrict__ out) {
    __shared__ __nv_bfloat16 sBh[64 * (ROWB / 2)];
    __shared__ __nv_bfloat16 sBl[64 * (ROWB / 2)];
    const uint32_t sbh = smem_u32(sBh);
    const uint32_t sbl = smem_u32(sBl);

    const int tid = threadIdx.x;
    const int w = tid >> 5;           // 0..7 -> m slice
    const int lane = tid & 31;
    const int g = lane >> 2;          // 0..7
    const int t = lane & 3;           // 0..3
    const int dBase = blockIdx.x * 64;
    const int bBase = blockIdx.y * 128;

    // --- stage B: 64 rows x 8 int4 (128 B) per row ---
    {
        const int4* __restrict__ bh = (const int4*)g_BT_hi;
        const int4* __restrict__ bl = (const int4*)g_BT_lo;
#pragma unroll
        for (int i = 0; i < 2; i++) {
            const int idx = i * 256 + tid;          // 0..511
            const int r = idx >> 3, c = idx & 7;
            const int off = r * ROWB + c * 16;
            *(int4*)((char*)sBh + off) = __ldg(&bh[(size_t)(dBase + r) * 8 + c]);
            *(int4*)((char*)sBl + off) = __ldg(&bl[(size_t)(dBase + r) * 8 + c]);
        }
    }
    __syncthreads();

    // ldmatrix lane address components
    const int lr = lane & 7;
    const int seg = lane >> 3;        // 0..3
    const int row_off = (seg & 1) * 8 + lr;
    const int k_off = (seg >> 1) * 8;

    const int m0 = bBase + w * 16;
    const uint32_t* __restrict__ Ah = (const uint32_t*)g_A_hi;  // [b][32] pairs
    const uint32_t* __restrict__ Al = (const uint32_t*)g_A_lo;
    const size_t rowA0 = (size_t)(m0 + g) * 32;
    const size_t rowA1 = (size_t)(m0 + 8 + g) * 32;

    float acc[8][4];
#pragma unroll
    for (int nt = 0; nt < 8; nt++)
#pragma unroll
        for (int q = 0; q < 4; q++) acc[nt][q] = 0.f;

#pragma unroll
    for (int ks = 0; ks < 4; ks++) {
        const int kp = ks * 8;                      // uint32-pair base
        uint32_t ah[4], al[4];
        ah[0] = __ldg(&Ah[rowA0 + kp + t]);
        ah[1] = __ldg(&Ah[rowA1 + kp + t]);
        ah[2] = __ldg(&Ah[rowA0 + kp + 4 + t]);
        ah[3] = __ldg(&Ah[rowA1 + kp + 4 + t]);
        al[0] = __ldg(&Al[rowA0 + kp + t]);
        al[1] = __ldg(&Al[rowA1 + kp + t]);
        al[2] = __ldg(&Al[rowA0 + kp + 4 + t]);
        al[3] = __ldg(&Al[rowA1 + kp + 4 + t]);

        const int kb = (ks * 16 + k_off) * 2;       // byte offset along k

#pragma unroll
        for (int p = 0; p < 4; p++) {               // covers nt = 2p, 2p+1
            const int n = p * 16 + row_off;
            uint32_t bh0, bh1, bh2, bh3, bl0, bl1, bl2, bl3;
            LDSM_X4(bh0, bh1, bh2, bh3, sbh + n * ROWB + kb);
            LDSM_X4(bl0, bl1, bl2, bl3, sbl + n * ROWB + kb);
            MMA16816(acc[2*p],   ah, bh0, bh2);
            MMA16816(acc[2*p],   ah, bl0, bl2);
            MMA16816(acc[2*p],   al, bh0, bh2);
            MMA16816(acc[2*p+1], ah, bh1, bh3);
            MMA16816(acc[2*p+1], ah, bl1, bl3);
            MMA16816(acc[2*p+1], al, bh1, bh3);
        }
    }

    // --- epilogue: direct float2 stores ---
    const int m = m0 + g;
#pragma unroll
    for (int nt = 0; nt < 8; nt++) {
        const int col = dBase + nt * 8 + t * 2;
        *(float2*)&out[(size_t)m * EMB_DIM + col] = make_float2(acc[nt][0], acc[nt][1]);
        *(float2*)&out[(size_t)(m + 8) * EMB_DIM + col] = make_float2(acc[nt][2], acc[nt][3]);
    }
}

// ---------------------------------------------------------------------------
// Launch
// ---------------------------------------------------------------------------
extern "C" void kernel_launch(void* const* d_in, const int* in_sizes, int n_in,
                              void* d_out, int out_size) {
    const int* ids = nullptr;
    const float* ratio = nullptr;
    const float* emb = nullptr;
    for (int i = 0; i < n_in; i++) {
        if (in_sizes[i] == N_COMP * SEQ_L)      ids   = (const int*)d_in[i];
        else if (in_sizes[i] == BATCH * N_COMP) ratio = (const float*)d_in[i];
        else                                     emb   = (const float*)d_in[i];
    }
    float* out = (float*)d_out;

    {   // pool partials
        dim3 grid(N_COMP, 4, SPLIT);            // 2048 blocks
        pool_kernel<<<grid, 128>>>(ids, emb);
    }
    {   // pooled reduce/split/transpose + ratio hi/lo
        cvt_kernel<<<320, 128>>>(ratio);
    }
    {   // HMMA mix
        dim3 grid(EMB_DIM / 64, BATCH / 128);   // (32, 32) = 1024 CTAs
        mix_kernel<<<grid, 256>>>(out);
    }
}

// round 9
// speedup vs baseline: 1.2339x; 1.2339x over previous
#include <cuda_runtime.h>
#include <cuda_bf16.h>
#include <cstdint>

#define VOCAB   32000
#define EMB_DIM 2048
#define N_COMP  64
#define SEQ_L   128
#define BATCH   4096
#define SPLIT   8

// ---------------------------------------------------------------------------
// Static scratch (no allocation)
// ---------------------------------------------------------------------------
__device__ float         g_part[SPLIT][N_COMP * EMB_DIM];   // pool partials (4 MB)
__device__ __nv_bfloat16 g_BT_hi[EMB_DIM * N_COMP];         // pooled^T hi [n][k]
__device__ __nv_bfloat16 g_BT_lo[EMB_DIM * N_COMP];         // pooled^T lo [n][k]

// ---------------------------------------------------------------------------
// Kernel 1: pooled partial sums. grid=(N_COMP, 4, SPLIT), block=128.
// ---------------------------------------------------------------------------
__global__ void pool_kernel(const int* __restrict__ ids,
                            const float* __restrict__ emb) {
    __shared__ int s_ids[SEQ_L / SPLIT];
    const int comp = blockIdx.x;
    const int z = blockIdx.z;
    const int t = threadIdx.x;
    const int TOK = SEQ_L / SPLIT;              // 16
    if (t < TOK) s_ids[t] = ids[comp * SEQ_L + z * TOK + t];
    __syncthreads();

    const int col4 = blockIdx.y * 128 + t;      // 0..511
    const float4* __restrict__ emb4 = (const float4*)emb;

    float4 acc = make_float4(0.f, 0.f, 0.f, 0.f);
#pragma unroll
    for (int l = 0; l < TOK; l++) {
        const int row = s_ids[l];
        float4 v = __ldg(&emb4[(size_t)row * (EMB_DIM / 4) + col4]);
        acc.x += v.x; acc.y += v.y; acc.z += v.z; acc.w += v.w;
    }
    ((float4*)g_part[z])[comp * (EMB_DIM / 4) + col4] = acc;
}

// ---------------------------------------------------------------------------
// bf16 split helpers
// ---------------------------------------------------------------------------
__device__ __forceinline__ void split_bf16(float v, __nv_bfloat16& hi, __nv_bfloat16& lo) {
    hi = __float2bfloat16_rn(v);
    lo = __float2bfloat16_rn(v - __bfloat162float(hi));
}
__device__ __forceinline__ uint32_t pack_bf2(__nv_bfloat16 a, __nv_bfloat16 b) {
    __nv_bfloat162 h = __halves2bfloat162(a, b);
    return *reinterpret_cast<uint32_t*>(&h);
}

// ---------------------------------------------------------------------------
// Kernel 2: pooled reduce + scale + bf16 split + transpose. grid=64, block=128.
// ---------------------------------------------------------------------------
__global__ void cvt_kernel() {
    const int lane = threadIdx.x & 31;
    const int ty = threadIdx.x >> 5;            // 0..3
    const int n = blockIdx.x * 32 + lane;       // 0..2047
    const int k0 = ty * 16;

    uint32_t h2[8], l2[8];
#pragma unroll
    for (int kp = 0; kp < 8; kp++) {
        __nv_bfloat16 ha, la, hb, lb;
        {
            const int k = k0 + 2 * kp;
            float s = 0.f;
#pragma unroll
            for (int z = 0; z < SPLIT; z++) s += g_part[z][k * EMB_DIM + n];
            split_bf16(s * (1.0f / SEQ_L), ha, la);
        }
        {
            const int k = k0 + 2 * kp + 1;
            float s = 0.f;
#pragma unroll
            for (int z = 0; z < SPLIT; z++) s += g_part[z][k * EMB_DIM + n];
            split_bf16(s * (1.0f / SEQ_L), hb, lb);
        }
        h2[kp] = pack_bf2(ha, hb);
        l2[kp] = pack_bf2(la, lb);
    }
    uint4* dh = (uint4*)g_BT_hi;   // row n = 8 uint4 (64 bf16)
    uint4* dl = (uint4*)g_BT_lo;
#pragma unroll
    for (int c = 0; c < 2; c++) {
        dh[n * 8 + ty * 2 + c] = make_uint4(h2[4*c], h2[4*c+1], h2[4*c+2], h2[4*c+3]);
        dl[n * 8 + ty * 2 + c] = make_uint4(l2[4*c], l2[4*c+1], l2[4*c+2], l2[4*c+3]);
    }
}

// ---------------------------------------------------------------------------
// Kernel 3: HMMA mix (R5 structure), MMA issue order interleaved so the
// same-accumulator dependency distance is 4 instructions instead of 1.
// CTA: 128 b-rows x 128 d-cols, 256 threads (4 warps m x 2 warps n).
// ---------------------------------------------------------------------------
#define MMA16816(c, a, b0, b1) \
    asm volatile("mma.sync.aligned.m16n8k16.row.col.f32.bf16.bf16.f32 " \
        "{%0,%1,%2,%3}, {%4,%5,%6,%7}, {%8,%9}, {%0,%1,%2,%3};" \
        : "+f"((c)[0]), "+f"((c)[1]), "+f"((c)[2]), "+f"((c)[3]) \
        : "r"((a)[0]), "r"((a)[1]), "r"((a)[2]), "r"((a)[3]), "r"(b0), "r"(b1))

#define LDSM_X4(r0, r1, r2, r3, addr) \
    asm volatile("ldmatrix.sync.aligned.m8n8.x4.shared.b16 {%0,%1,%2,%3}, [%4];" \
        : "=r"(r0), "=r"(r1), "=r"(r2), "=r"(r3) : "r"(addr))

#define ROWB 144            // padded row pitch in bytes (72 bf16)
#define OFF_AH 0
#define OFF_AL (128 * ROWB)
#define OFF_BH (2 * 128 * ROWB)
#define OFF_BL (3 * 128 * ROWB)
#define MIX_SMEM (4 * 128 * ROWB)   // 73728 B

__device__ __forceinline__ uint32_t smem_u32(const void* p) {
    uint32_t a;
    asm("{ .reg .u64 t; cvta.to.shared.u64 t, %1; cvt.u32.u64 %0, t; }" : "=r"(a) : "l"(p));
    return a;
}

__global__ void __launch_bounds__(256)
mix_kernel(const float* __restrict__ ratio, float* __restrict__ out) {
    extern __shared__ char smem[];
    const uint32_t sb = smem_u32(smem);

    const int tid = threadIdx.x;
    const int wid = tid >> 5;
    const int lane = tid & 31;
    const int g = lane >> 2;          // 0..7
    const int t = lane & 3;           // 0..3
    const int dBase = blockIdx.x * 128;
    const int bBase = blockIdx.y * 128;

    // --- stage A: ratio[bBase..+128][0..64] fp32 -> bf16 hi/lo in smem ---
    {
        const float4* __restrict__ rg = (const float4*)ratio;
#pragma unroll
        for (int i = 0; i < 8; i++) {
            const int idx = i * 256 + tid;          // 0..2047
            const int b = idx >> 4;                 // row 0..127
            const int c = idx & 15;                 // float4 (4 cols)
            float4 v = __ldg(&rg[(size_t)(bBase + b) * 16 + c]);
            __nv_bfloat16 h0, l0, h1, l1, h2, l2, h3, l3;
            split_bf16(v.x, h0, l0); split_bf16(v.y, h1, l1);
            split_bf16(v.z, h2, l2); split_bf16(v.w, h3, l3);
            const int off = b * ROWB + c * 8;
            *(uint2*)(smem + OFF_AH + off) = make_uint2(pack_bf2(h0, h1), pack_bf2(h2, h3));
            *(uint2*)(smem + OFF_AL + off) = make_uint2(pack_bf2(l0, l1), pack_bf2(l2, l3));
        }
    }
    // --- stage B: g_BT rows dBase..+128, 8 int4 per row ---
    {
        const int4* __restrict__ bh = (const int4*)g_BT_hi;
        const int4* __restrict__ bl = (const int4*)g_BT_lo;
#pragma unroll
        for (int i = 0; i < 4; i++) {
            const int idx = i * 256 + tid;          // 0..1023
            const int r = idx >> 3, c = idx & 7;
            const int off = r * ROWB + c * 16;
            *(int4*)(smem + OFF_BH + off) = __ldg(&bh[(size_t)(dBase + r) * 8 + c]);
            *(int4*)(smem + OFF_BL + off) = __ldg(&bl[(size_t)(dBase + r) * 8 + c]);
        }
    }
    __syncthreads();

    const int wm = wid & 3;           // m warp (0..3)
    const int wn = wid >> 2;          // n warp (0..1)

    // ldmatrix lane address components
    const int lr = lane & 7;
    const int seg = lane >> 3;        // 0..3
    const int row_off = (seg & 1) * 8 + lr;
    const int k_off = (seg >> 1) * 8;

    float acc[2][8][4];
#pragma unroll
    for (int mt = 0; mt < 2; mt++)
#pragma unroll
        for (int nt = 0; nt < 8; nt++)
#pragma unroll
            for (int q = 0; q < 4; q++) acc[mt][nt][q] = 0.f;

#pragma unroll
    for (int ks = 0; ks < 4; ks++) {
        const int kb = (ks * 16 + k_off) * 2;       // byte offset along k

        uint32_t ah[2][4], al[2][4];
#pragma unroll
        for (int mt = 0; mt < 2; mt++) {
            const int m = wm * 32 + mt * 16 + row_off;
            LDSM_X4(ah[mt][0], ah[mt][1], ah[mt][2], ah[mt][3], sb + OFF_AH + m * ROWB + kb);
            LDSM_X4(al[mt][0], al[mt][1], al[mt][2], al[mt][3], sb + OFF_AL + m * ROWB + kb);
        }

#pragma unroll
        for (int p = 0; p < 4; p++) {               // covers nt = 2p, 2p+1
            const int n = wn * 64 + p * 16 + row_off;
            uint32_t bh0, bh1, bh2, bh3, bl0, bl1, bl2, bl3;
            LDSM_X4(bh0, bh1, bh2, bh3, sb + OFF_BH + n * ROWB + kb);
            LDSM_X4(bl0, bl1, bl2, bl3, sb + OFF_BL + n * ROWB + kb);
            // Interleaved: same-acc dependency distance = 4 MMAs.
            MMA16816(acc[0][2*p],   ah[0], bh0, bh2);   // hh
            MMA16816(acc[1][2*p],   ah[1], bh0, bh2);
            MMA16816(acc[0][2*p+1], ah[0], bh1, bh3);
            MMA16816(acc[1][2*p+1], ah[1], bh1, bh3);
            MMA16816(acc[0][2*p],   ah[0], bl0, bl2);   // hl
            MMA16816(acc[1][2*p],   ah[1], bl0, bl2);
            MMA16816(acc[0][2*p+1], ah[0], bl1, bl3);
            MMA16816(acc[1][2*p+1], ah[1], bl1, bl3);
            MMA16816(acc[0][2*p],   al[0], bh0, bh2);   // lh
            MMA16816(acc[1][2*p],   al[1], bh0, bh2);
            MMA16816(acc[0][2*p+1], al[0], bh1, bh3);
            MMA16816(acc[1][2*p+1], al[1], bh1, bh3);
        }
    }

    // --- epilogue: direct float2 stores ---
#pragma unroll
    for (int mt = 0; mt < 2; mt++) {
        const int m = bBase + wm * 32 + mt * 16 + g;
#pragma unroll
        for (int nt = 0; nt < 8; nt++) {
            const int col = dBase + wn * 64 + nt * 8 + t * 2;
            *(float2*)&out[(size_t)m * EMB_DIM + col] =
                make_float2(acc[mt][nt][0], acc[mt][nt][1]);
            *(float2*)&out[(size_t)(m + 8) * EMB_DIM + col] =
                make_float2(acc[mt][nt][2], acc[mt][nt][3]);
        }
    }
}

// ---------------------------------------------------------------------------
// Launch
// ---------------------------------------------------------------------------
extern "C" void kernel_launch(void* const* d_in, const int* in_sizes, int n_in,
                              void* d_out, int out_size) {
    const int* ids = nullptr;
    const float* ratio = nullptr;
    const float* emb = nullptr;
    for (int i = 0; i < n_in; i++) {
        if (in_sizes[i] == N_COMP * SEQ_L)      ids   = (const int*)d_in[i];
        else if (in_sizes[i] == BATCH * N_COMP) ratio = (const float*)d_in[i];
        else                                     emb   = (const float*)d_in[i];
    }
    float* out = (float*)d_out;

    {   // pool partials
        dim3 grid(N_COMP, 4, SPLIT);            // 2048 blocks
        pool_kernel<<<grid, 128>>>(ids, emb);
    }
    {   // pooled reduce/split/transpose
        cvt_kernel<<<64, 128>>>();
    }
    {   // HMMA mix
        static bool attr_set = false;
        if (!attr_set) {
            cudaFuncSetAttribute(mix_kernel,
                                 cudaFuncAttributeMaxDynamicSharedMemorySize,
                                 MIX_SMEM);
            attr_set = true;
        }
        dim3 grid(EMB_DIM / 128, BATCH / 128);  // (16, 32)
        mix_kernel<<<grid, 256, MIX_SMEM>>>(ratio, out);
    }
}

// round 10
// speedup vs baseline: 1.3299x; 1.0778x over previous
#include <cuda_runtime.h>
#include <cuda_fp16.h>
#include <cstdint>

#define VOCAB   32000
#define EMB_DIM 2048
#define N_COMP  64
#define SEQ_L   128
#define BATCH   4096
#define SPLIT   8

// ---------------------------------------------------------------------------
// Static scratch (no allocation)
// ---------------------------------------------------------------------------
__device__ float  g_part[SPLIT][N_COMP * EMB_DIM];   // pool partials (4 MB)
__device__ __half g_BT[EMB_DIM * N_COMP];            // pooled^T fp16 [n][k]

// ---------------------------------------------------------------------------
// Kernel 1: pooled partial sums. grid=(N_COMP, 4, SPLIT), block=128.
// ---------------------------------------------------------------------------
__global__ void pool_kernel(const int* __restrict__ ids,
                            const float* __restrict__ emb) {
    __shared__ int s_ids[SEQ_L / SPLIT];
    const int comp = blockIdx.x;
    const int z = blockIdx.z;
    const int t = threadIdx.x;
    const int TOK = SEQ_L / SPLIT;              // 16
    if (t < TOK) s_ids[t] = ids[comp * SEQ_L + z * TOK + t];
    __syncthreads();

    const int col4 = blockIdx.y * 128 + t;      // 0..511
    const float4* __restrict__ emb4 = (const float4*)emb;

    float4 acc = make_float4(0.f, 0.f, 0.f, 0.f);
#pragma unroll
    for (int l = 0; l < TOK; l++) {
        const int row = s_ids[l];
        float4 v = __ldg(&emb4[(size_t)row * (EMB_DIM / 4) + col4]);
        acc.x += v.x; acc.y += v.y; acc.z += v.z; acc.w += v.w;
    }
    ((float4*)g_part[z])[comp * (EMB_DIM / 4) + col4] = acc;
}

// ---------------------------------------------------------------------------
// fp16 helpers
// ---------------------------------------------------------------------------
__device__ __forceinline__ void split_f16(float v, __half& hi, __half& lo) {
    hi = __float2half_rn(v);
    lo = __float2half_rn(v - __half2float(hi));
}
__device__ __forceinline__ uint32_t pack_h2(__half a, __half b) {
    __half2 h = __halves2half2(a, b);
    return *reinterpret_cast<uint32_t*>(&h);
}

// ---------------------------------------------------------------------------
// Kernel 2: pooled reduce + scale + fp16 round + transpose. grid=64, block=128.
// ---------------------------------------------------------------------------
__global__ void cvt_kernel() {
    const int lane = threadIdx.x & 31;
    const int ty = threadIdx.x >> 5;            // 0..3
    const int n = blockIdx.x * 32 + lane;       // 0..2047
    const int k0 = ty * 16;

    uint32_t h2[8];
#pragma unroll
    for (int kp = 0; kp < 8; kp++) {
        float sa = 0.f, sb = 0.f;
#pragma unroll
        for (int z = 0; z < SPLIT; z++) {
            sa += g_part[z][(k0 + 2 * kp) * EMB_DIM + n];
            sb += g_part[z][(k0 + 2 * kp + 1) * EMB_DIM + n];
        }
        h2[kp] = pack_h2(__float2half_rn(sa * (1.0f / SEQ_L)),
                         __float2half_rn(sb * (1.0f / SEQ_L)));
    }
    uint4* dh = (uint4*)g_BT;      // row n = 8 uint4 (64 fp16)
#pragma unroll
    for (int c = 0; c < 2; c++) {
        dh[n * 8 + ty * 2 + c] = make_uint4(h2[4*c], h2[4*c+1], h2[4*c+2], h2[4*c+3]);
    }
}

// ---------------------------------------------------------------------------
// Kernel 3: HMMA mix, fp16 2-product scheme.
// out = (rh + rl) @ ph :  A (ratio) exact via fp16 hi/lo split, B rounded fp16.
// CTA: 128 b-rows x 128 d-cols, 256 threads (4 warps m x 2 warps n).
// Per warp per k-step: 2 A-LDSM x2 + 4 B-LDSM, 32 MMA (interleaved, dist 4).
// ---------------------------------------------------------------------------
#define MMA16816(c, a, b0, b1) \
    asm volatile("mma.sync.aligned.m16n8k16.row.col.f32.f16.f16.f32 " \
        "{%0,%1,%2,%3}, {%4,%5,%6,%7}, {%8,%9}, {%0,%1,%2,%3};" \
        : "+f"((c)[0]), "+f"((c)[1]), "+f"((c)[2]), "+f"((c)[3]) \
        : "r"((a)[0]), "r"((a)[1]), "r"((a)[2]), "r"((a)[3]), "r"(b0), "r"(b1))

#define LDSM_X4(r0, r1, r2, r3, addr) \
    asm volatile("ldmatrix.sync.aligned.m8n8.x4.shared.b16 {%0,%1,%2,%3}, [%4];" \
        : "=r"(r0), "=r"(r1), "=r"(r2), "=r"(r3) : "r"(addr))

#define ROWB 144            // padded row pitch in bytes (72 halves)
#define OFF_AH 0
#define OFF_AL (128 * ROWB)
#define OFF_B  (2 * 128 * ROWB)
#define MIX_SMEM (3 * 128 * ROWB)   // 55296 B

__device__ __forceinline__ uint32_t smem_u32(const void* p) {
    uint32_t a;
    asm("{ .reg .u64 t; cvta.to.shared.u64 t, %1; cvt.u32.u64 %0, t; }" : "=r"(a) : "l"(p));
    return a;
}

__global__ void __launch_bounds__(256)
mix_kernel(const float* __restrict__ ratio, float* __restrict__ out) {
    extern __shared__ char smem[];
    const uint32_t sb = smem_u32(smem);

    const int tid = threadIdx.x;
    const int wid = tid >> 5;
    const int lane = tid & 31;
    const int g = lane >> 2;          // 0..7
    const int t = lane & 3;           // 0..3
    const int dBase = blockIdx.x * 128;
    const int bBase = blockIdx.y * 128;

    // --- stage A: ratio[bBase..+128][0..64] fp32 -> fp16 hi/lo in smem ---
    {
        const float4* __restrict__ rg = (const float4*)ratio;
#pragma unroll
        for (int i = 0; i < 8; i++) {
            const int idx = i * 256 + tid;          // 0..2047
            const int b = idx >> 4;                 // row 0..127
            const int c = idx & 15;                 // float4 (4 cols)
            float4 v = __ldg(&rg[(size_t)(bBase + b) * 16 + c]);
            __half h0, l0, h1, l1, h2, l2, h3, l3;
            split_f16(v.x, h0, l0); split_f16(v.y, h1, l1);
            split_f16(v.z, h2, l2); split_f16(v.w, h3, l3);
            const int off = b * ROWB + c * 8;
            *(uint2*)(smem + OFF_AH + off) = make_uint2(pack_h2(h0, h1), pack_h2(h2, h3));
            *(uint2*)(smem + OFF_AL + off) = make_uint2(pack_h2(l0, l1), pack_h2(l2, l3));
        }
    }
    // --- stage B: g_BT rows dBase..+128, 8 int4 per row ---
    {
        const int4* __restrict__ bh = (const int4*)g_BT;
#pragma unroll
        for (int i = 0; i < 4; i++) {
            const int idx = i * 256 + tid;          // 0..1023
            const int r = idx >> 3, c = idx & 7;
            *(int4*)(smem + OFF_B + r * ROWB + c * 16) =
                __ldg(&bh[(size_t)(dBase + r) * 8 + c]);
        }
    }
    __syncthreads();

    const int wm = wid & 3;           // m warp (0..3)
    const int wn = wid >> 2;          // n warp (0..1)

    // ldmatrix lane address components
    const int lr = lane & 7;
    const int seg = lane >> 3;        // 0..3
    const int row_off = (seg & 1) * 8 + lr;
    const int k_off = (seg >> 1) * 8;

    float acc[2][8][4];
#pragma unroll
    for (int mt = 0; mt < 2; mt++)
#pragma unroll
        for (int nt = 0; nt < 8; nt++)
#pragma unroll
            for (int q = 0; q < 4; q++) acc[mt][nt][q] = 0.f;

#pragma unroll
    for (int ks = 0; ks < 4; ks++) {
        const int kb = (ks * 16 + k_off) * 2;       // byte offset along k

        uint32_t ah[2][4], al[2][4];
#pragma unroll
        for (int mt = 0; mt < 2; mt++) {
            const int m = wm * 32 + mt * 16 + row_off;
            LDSM_X4(ah[mt][0], ah[mt][1], ah[mt][2], ah[mt][3], sb + OFF_AH + m * ROWB + kb);
            LDSM_X4(al[mt][0], al[mt][1], al[mt][2], al[mt][3], sb + OFF_AL + m * ROWB + kb);
        }

#pragma unroll
        for (int p = 0; p < 4; p++) {               // covers nt = 2p, 2p+1
            const int n = wn * 64 + p * 16 + row_off;
            uint32_t b0, b1, b2, b3;
            LDSM_X4(b0, b1, b2, b3, sb + OFF_B + n * ROWB + kb);
            // Interleaved: same-acc dependency distance = 4 MMAs.
            MMA16816(acc[0][2*p],   ah[0], b0, b2);     // rh * ph
            MMA16816(acc[1][2*p],   ah[1], b0, b2);
            MMA16816(acc[0][2*p+1], ah[0], b1, b3);
            MMA16816(acc[1][2*p+1], ah[1], b1, b3);
            MMA16816(acc[0][2*p],   al[0], b0, b2);     // rl * ph
            MMA16816(acc[1][2*p],   al[1], b0, b2);
            MMA16816(acc[0][2*p+1], al[0], b1, b3);
            MMA16816(acc[1][2*p+1], al[1], b1, b3);
        }
    }

    // --- epilogue: direct float2 stores ---
#pragma unroll
    for (int mt = 0; mt < 2; mt++) {
        const int m = bBase + wm * 32 + mt * 16 + g;
#pragma unroll
        for (int nt = 0; nt < 8; nt++) {
            const int col = dBase + wn * 64 + nt * 8 + t * 2;
            *(float2*)&out[(size_t)m * EMB_DIM + col] =
                make_float2(acc[mt][nt][0], acc[mt][nt][1]);
            *(float2*)&out[(size_t)(m + 8) * EMB_DIM + col] =
                make_float2(acc[mt][nt][2], acc[mt][nt][3]);
        }
    }
}

// ---------------------------------------------------------------------------
// Launch
// ---------------------------------------------------------------------------
extern "C" void kernel_launch(void* const* d_in, const int* in_sizes, int n_in,
                              void* d_out, int out_size) {
    const int* ids = nullptr;
    const float* ratio = nullptr;
    const float* emb = nullptr;
    for (int i = 0; i < n_in; i++) {
        if (in_sizes[i] == N_COMP * SEQ_L)      ids   = (const int*)d_in[i];
        else if (in_sizes[i] == BATCH * N_COMP) ratio = (const float*)d_in[i];
        else                                     emb   = (const float*)d_in[i];
    }
    float* out = (float*)d_out;

    {   // pool partials
        dim3 grid(N_COMP, 4, SPLIT);            // 2048 blocks
        pool_kernel<<<grid, 128>>>(ids, emb);
    }
    {   // pooled reduce/round/transpose
        cvt_kernel<<<64, 128>>>();
    }
    {   // HMMA mix (fp16, 2 products)
        static bool attr_set = false;
        if (!attr_set) {
            cudaFuncSetAttribute(mix_kernel,
                                 cudaFuncAttributeMaxDynamicSharedMemorySize,
                                 MIX_SMEM);
            attr_set = true;
        }
        dim3 grid(EMB_DIM / 128, BATCH / 128);  // (16, 32)
        mix_kernel<<<grid, 256, MIX_SMEM>>>(ratio, out);
    }
}

// round 11
// speedup vs baseline: 1.5136x; 1.1381x over previous
#include <cuda_runtime.h>
#include <cuda_fp16.h>
#include <cstdint>

#define VOCAB   32000
#define EMB_DIM 2048
#define N_COMP  64
#define SEQ_L   128
#define BATCH   4096
#define SPLIT   8

// ---------------------------------------------------------------------------
// Static scratch (no allocation)
// ---------------------------------------------------------------------------
__device__ float  g_part[SPLIT][N_COMP * EMB_DIM];   // pool partials (4 MB)
__device__ __half g_BT[EMB_DIM * N_COMP];            // pooled^T fp16 [n][k]

// ---------------------------------------------------------------------------
// Kernel 1: pooled partial sums. grid=(N_COMP, 4, SPLIT), block=128.
// ---------------------------------------------------------------------------
__global__ void pool_kernel(const int* __restrict__ ids,
                            const float* __restrict__ emb) {
    __shared__ int s_ids[SEQ_L / SPLIT];
    const int comp = blockIdx.x;
    const int z = blockIdx.z;
    const int t = threadIdx.x;
    const int TOK = SEQ_L / SPLIT;              // 16
    if (t < TOK) s_ids[t] = ids[comp * SEQ_L + z * TOK + t];
    __syncthreads();

    const int col4 = blockIdx.y * 128 + t;      // 0..511
    const float4* __restrict__ emb4 = (const float4*)emb;

    float4 acc = make_float4(0.f, 0.f, 0.f, 0.f);
#pragma unroll
    for (int l = 0; l < TOK; l++) {
        const int row = s_ids[l];
        float4 v = __ldg(&emb4[(size_t)row * (EMB_DIM / 4) + col4]);
        acc.x += v.x; acc.y += v.y; acc.z += v.z; acc.w += v.w;
    }
    ((float4*)g_part[z])[comp * (EMB_DIM / 4) + col4] = acc;
}

// ---------------------------------------------------------------------------
// fp16 helpers
// ---------------------------------------------------------------------------
__device__ __forceinline__ uint32_t pack_h2(__half a, __half b) {
    __half2 h = __halves2half2(a, b);
    return *reinterpret_cast<uint32_t*>(&h);
}

// ---------------------------------------------------------------------------
// Kernel 2: pooled reduce + scale + fp16 round + transpose. grid=64, block=128.
// ---------------------------------------------------------------------------
__global__ void cvt_kernel() {
    const int lane = threadIdx.x & 31;
    const int ty = threadIdx.x >> 5;            // 0..3
    const int n = blockIdx.x * 32 + lane;       // 0..2047
    const int k0 = ty * 16;

    uint32_t h2[8];
#pragma unroll
    for (int kp = 0; kp < 8; kp++) {
        float sa = 0.f, sb = 0.f;
#pragma unroll
        for (int z = 0; z < SPLIT; z++) {
            sa += g_part[z][(k0 + 2 * kp) * EMB_DIM + n];
            sb += g_part[z][(k0 + 2 * kp + 1) * EMB_DIM + n];
        }
        h2[kp] = pack_h2(__float2half_rn(sa * (1.0f / SEQ_L)),
                         __float2half_rn(sb * (1.0f / SEQ_L)));
    }
    uint4* dh = (uint4*)g_BT;      // row n = 8 uint4 (64 fp16)
#pragma unroll
    for (int c = 0; c < 2; c++) {
        dh[n * 8 + ty * 2 + c] = make_uint4(h2[4*c], h2[4*c+1], h2[4*c+2], h2[4*c+3]);
    }
}

// ---------------------------------------------------------------------------
// Kernel 3: HMMA mix, single-product fp16 (both operands rounded).
// CTA: 128 b-rows x 128 d-cols, 256 threads (4 warps m x 2 warps n).
// Per warp per k-step: 2 A-LDSM + 4 B-LDSM, 16 MMA (acc reuse distance 16).
// ---------------------------------------------------------------------------
#define MMA16816(c, a, b0, b1) \
    asm volatile("mma.sync.aligned.m16n8k16.row.col.f32.f16.f16.f32 " \
        "{%0,%1,%2,%3}, {%4,%5,%6,%7}, {%8,%9}, {%0,%1,%2,%3};" \
        : "+f"((c)[0]), "+f"((c)[1]), "+f"((c)[2]), "+f"((c)[3]) \
        : "r"((a)[0]), "r"((a)[1]), "r"((a)[2]), "r"((a)[3]), "r"(b0), "r"(b1))

#define LDSM_X4(r0, r1, r2, r3, addr) \
    asm volatile("ldmatrix.sync.aligned.m8n8.x4.shared.b16 {%0,%1,%2,%3}, [%4];" \
        : "=r"(r0), "=r"(r1), "=r"(r2), "=r"(r3) : "r"(addr))

#define ROWB 144            // padded row pitch in bytes (72 halves)
#define OFF_A  0
#define OFF_B  (128 * ROWB)
#define MIX_SMEM (2 * 128 * ROWB)   // 36864 B

__device__ __forceinline__ uint32_t smem_u32(const void* p) {
    uint32_t a;
    asm("{ .reg .u64 t; cvta.to.shared.u64 t, %1; cvt.u32.u64 %0, t; }" : "=r"(a) : "l"(p));
    return a;
}

__global__ void __launch_bounds__(256)
mix_kernel(const float* __restrict__ ratio, float* __restrict__ out) {
    extern __shared__ char smem[];
    const uint32_t sb = smem_u32(smem);

    const int tid = threadIdx.x;
    const int wid = tid >> 5;
    const int lane = tid & 31;
    const int g = lane >> 2;          // 0..7
    const int t = lane & 3;           // 0..3
    const int dBase = blockIdx.x * 128;
    const int bBase = blockIdx.y * 128;

    // --- stage A: ratio[bBase..+128][0..64] fp32 -> fp16 (rounded) in smem ---
    {
        const float4* __restrict__ rg = (const float4*)ratio;
#pragma unroll
        for (int i = 0; i < 8; i++) {
            const int idx = i * 256 + tid;          // 0..2047
            const int b = idx >> 4;                 // row 0..127
            const int c = idx & 15;                 // float4 (4 cols)
            float4 v = __ldg(&rg[(size_t)(bBase + b) * 16 + c]);
            const int off = b * ROWB + c * 8;
            *(uint2*)(smem + OFF_A + off) =
                make_uint2(pack_h2(__float2half_rn(v.x), __float2half_rn(v.y)),
                           pack_h2(__float2half_rn(v.z), __float2half_rn(v.w)));
        }
    }
    // --- stage B: g_BT rows dBase..+128, 8 int4 per row ---
    {
        const int4* __restrict__ bh = (const int4*)g_BT;
#pragma unroll
        for (int i = 0; i < 4; i++) {
            const int idx = i * 256 + tid;          // 0..1023
            const int r = idx >> 3, c = idx & 7;
            *(int4*)(smem + OFF_B + r * ROWB + c * 16) =
                __ldg(&bh[(size_t)(dBase + r) * 8 + c]);
        }
    }
    __syncthreads();

    const int wm = wid & 3;           // m warp (0..3)
    const int wn = wid >> 2;          // n warp (0..1)

    // ldmatrix lane address components
    const int lr = lane & 7;
    const int seg = lane >> 3;        // 0..3
    const int row_off = (seg & 1) * 8 + lr;
    const int k_off = (seg >> 1) * 8;

    float acc[2][8][4];
#pragma unroll
    for (int mt = 0; mt < 2; mt++)
#pragma unroll
        for (int nt = 0; nt < 8; nt++)
#pragma unroll
            for (int q = 0; q < 4; q++) acc[mt][nt][q] = 0.f;

#pragma unroll
    for (int ks = 0; ks < 4; ks++) {
        const int kb = (ks * 16 + k_off) * 2;       // byte offset along k

        uint32_t ah[2][4];
#pragma unroll
        for (int mt = 0; mt < 2; mt++) {
            const int m = wm * 32 + mt * 16 + row_off;
            LDSM_X4(ah[mt][0], ah[mt][1], ah[mt][2], ah[mt][3], sb + OFF_A + m * ROWB + kb);
        }

#pragma unroll
        for (int p = 0; p < 4; p++) {               // covers nt = 2p, 2p+1
            const int n = wn * 64 + p * 16 + row_off;
            uint32_t b0, b1, b2, b3;
            LDSM_X4(b0, b1, b2, b3, sb + OFF_B + n * ROWB + kb);
            MMA16816(acc[0][2*p],   ah[0], b0, b2);
            MMA16816(acc[1][2*p],   ah[1], b0, b2);
            MMA16816(acc[0][2*p+1], ah[0], b1, b3);
            MMA16816(acc[1][2*p+1], ah[1], b1, b3);
        }
    }

    // --- epilogue: direct float2 stores ---
#pragma unroll
    for (int mt = 0; mt < 2; mt++) {
        const int m = bBase + wm * 32 + mt * 16 + g;
#pragma unroll
        for (int nt = 0; nt < 8; nt++) {
            const int col = dBase + wn * 64 + nt * 8 + t * 2;
            *(float2*)&out[(size_t)m * EMB_DIM + col] =
                make_float2(acc[mt][nt][0], acc[mt][nt][1]);
            *(float2*)&out[(size_t)(m + 8) * EMB_DIM + col] =
                make_float2(acc[mt][nt][2], acc[mt][nt][3]);
        }
    }
}

// ---------------------------------------------------------------------------
// Launch
// ---------------------------------------------------------------------------
extern "C" void kernel_launch(void* const* d_in, const int* in_sizes, int n_in,
                              void* d_out, int out_size) {
    const int* ids = nullptr;
    const float* ratio = nullptr;
    const float* emb = nullptr;
    for (int i = 0; i < n_in; i++) {
        if (in_sizes[i] == N_COMP * SEQ_L)      ids   = (const int*)d_in[i];
        else if (in_sizes[i] == BATCH * N_COMP) ratio = (const float*)d_in[i];
        else                                     emb   = (const float*)d_in[i];
    }
    float* out = (float*)d_out;

    {   // pool partials
        dim3 grid(N_COMP, 4, SPLIT);            // 2048 blocks
        pool_kernel<<<grid, 128>>>(ids, emb);
    }
    {   // pooled reduce/round/transpose
        cvt_kernel<<<64, 128>>>();
    }
    {   // HMMA mix (fp16, single product)
        static bool attr_set = false;
        if (!attr_set) {
            cudaFuncSetAttribute(mix_kernel,
                                 cudaFuncAttributeMaxDynamicSharedMemorySize,
                                 MIX_SMEM);
            attr_set = true;
        }
        dim3 grid(EMB_DIM / 128, BATCH / 128);  // (16, 32)
        mix_kernel<<<grid, 256, MIX_SMEM>>>(ratio, out);
    }
}